// round 8
// baseline (speedup 1.0000x reference)
#include <cuda_runtime.h>
#include <cuda_fp16.h>
#include <cstdint>

#define NN 100000
#define NE 3200000
#define ET (NE + NN)
#define DIN 512
#define DH 64
#define NBLK 98

__device__ __half g_hs1[(size_t)NN * DH];
__device__ __half g_hs2[(size_t)NN * DH];
__device__ float g_bpk[80 * 32 * 20];
__device__ float g_dinv[NN];
__device__ int   g_cnt[NN];
__device__ int   g_rowptr[NN + 1];
__device__ int   g_cursor[NN];
__device__ int   g_col[ET];
__device__ int   g_bsum[128];

__device__ __forceinline__ uint32_t smem_u32(const void* p) {
    uint32_t a;
    asm("{ .reg .u64 t; cvta.to.shared.u64 t, %1; cvt.u32.u64 %0, t; }" : "=r"(a) : "l"(p));
    return a;
}
__device__ __forceinline__ void cpa16(float* dst, const float* src) {
    uint32_t d = smem_u32(dst);
    asm volatile("cp.async.ca.shared.global [%0], [%1], 16;" :: "r"(d), "l"(src) : "memory");
}
__device__ __forceinline__ void cpa_commit() {
    asm volatile("cp.async.commit_group;" ::: "memory");
}
template <int N> __device__ __forceinline__ void cpa_wait() {
    asm volatile("cp.async.wait_group %0;" :: "n"(N) : "memory");
}
__device__ __forceinline__ uint32_t f2tf32(float f) {
    uint32_t u;
    asm("cvt.rna.tf32.f32 %0, %1;" : "=r"(u) : "f"(f));
    return u;
}

__global__ void k_pack(const float* __restrict__ W1, const float* __restrict__ W2,
                       const float* __restrict__ Wlin) {
    int tid = blockIdx.x * blockDim.x + threadIdx.x;
    if (tid >= 80 * 32 * 16) return;
    int s   = tid >> 9;
    int l   = (tid >> 4) & 31;
    int idx = tid & 15;
    int g = l >> 2, tig = l & 3;
    int j = idx & 7;
    int half = idx >> 3;
    const float* W; int sl;
    if (s < 64)      { W = W1;   sl = s; }
    else if (s < 72) { W = W2;   sl = s - 64; }
    else             { W = Wlin; sl = s - 72; }
    int k = sl * 8 + tig + half * 4;
    float v = W[k * DH + 8 * j + g];
    g_bpk[(s * 32 + l) * 20 + idx] = __uint_as_float(f2tf32(v));
}

__global__ void k_init() {
    int i = blockIdx.x * blockDim.x + threadIdx.x;
    if (i < NN) g_cnt[i] = 0;
}

__global__ void k_count(const int* __restrict__ ei) {
    int e = blockIdx.x * blockDim.x + threadIdx.x;
    if (e >= ET) return;
    int d = (e < NE) ? ei[NE + e] : (e - NE);
    atomicAdd(&g_cnt[d], 1);
}

__global__ void k_scan1() {
    __shared__ int s[1024];
    int i = blockIdx.x * 1024 + threadIdx.x;
    int v = (i < NN) ? g_cnt[i] : 0;
    s[threadIdx.x] = v;
    __syncthreads();
    for (int off = 1; off < 1024; off <<= 1) {
        int t = (threadIdx.x >= off) ? s[threadIdx.x - off] : 0;
        __syncthreads();
        s[threadIdx.x] += t;
        __syncthreads();
    }
    if (i < NN) g_rowptr[i] = s[threadIdx.x] - v;
    if (threadIdx.x == 1023) g_bsum[blockIdx.x] = s[1023];
}

__global__ void k_scan2() {
    __shared__ int s[128];
    int t = threadIdx.x;
    int v = (t < NBLK) ? g_bsum[t] : 0;
    s[t] = v;
    __syncthreads();
    for (int off = 1; off < 128; off <<= 1) {
        int u = (t >= off) ? s[t - off] : 0;
        __syncthreads();
        s[t] += u;
        __syncthreads();
    }
    if (t < NBLK) g_bsum[t] = s[t] - v;
}

__global__ void k_scan3() {
    int i = blockIdx.x * blockDim.x + threadIdx.x;
    if (i == 0) g_rowptr[NN] = ET;
    if (i >= NN) return;
    int r = g_rowptr[i] + g_bsum[i >> 10];
    g_rowptr[i] = r;
    g_cursor[i] = r;
    g_dinv[i]   = rsqrtf((float)g_cnt[i]);
}

__global__ void k_fill(const int* __restrict__ ei) {
    int e = blockIdx.x * blockDim.x + threadIdx.x;
    if (e >= ET) return;
    int s, d;
    if (e < NE) { s = ei[e]; d = ei[NE + e]; } else { s = e - NE; d = s; }
    int pos = atomicAdd(&g_cursor[d], 1);
    g_col[pos] = s;
}

// ---------------- GEMM1 (round-6 config: M=256, 256 thr, 2 CTA/SM) -------
#define AST 36
#define SA_W (256 * AST)
#define SB_W 2560
#define GEMM_SMEM ((2 * SA_W + 2 * SB_W) * 4)   // 94208

__global__ __launch_bounds__(256) void k_gemm1_mma(const float* __restrict__ x) {
    extern __shared__ float sm[];
    float* sA[2] = {sm, sm + SA_W};
    float* sB[2] = {sm + 2 * SA_W, sm + 2 * SA_W + SB_W};
    int t = threadIdx.x;
    int wid = t >> 5, lane = t & 31;
    int g = lane >> 2, tig = lane & 3;
    int row0 = blockIdx.x * 256 + wid * 32;

    float c[2][8][4];
#pragma unroll
    for (int m = 0; m < 2; m++)
#pragma unroll
        for (int j = 0; j < 8; j++)
#pragma unroll
            for (int q = 0; q < 4; q++) c[m][j][q] = 0.f;

    int arow = t >> 3, ajj = t & 7;
    int argl = blockIdx.x * 256 + arow;

    {
#pragma unroll
        for (int p = 0; p < 8; p++) {
            int row = p * 32 + arow;
            int rg = argl + p * 32; if (rg >= NN) rg = NN - 1;
            cpa16(&sA[0][row * AST + ajj * 4], &x[(size_t)rg * DIN + ajj * 4]);
        }
#pragma unroll
        for (int q = 0; q < 3; q++) {
            int i = q * 256 + t;
            if (i < 640) cpa16(&sB[0][i * 4], &g_bpk[i * 4]);
        }
        cpa_commit();
    }

    for (int ch = 0; ch < 16; ch++) {
        int st = ch & 1;
        if (ch < 15) {
            int cn = ch + 1, sn = cn & 1;
#pragma unroll
            for (int p = 0; p < 8; p++) {
                int row = p * 32 + arow;
                int rg = argl + p * 32; if (rg >= NN) rg = NN - 1;
                cpa16(&sA[sn][row * AST + ajj * 4], &x[(size_t)rg * DIN + cn * 32 + ajj * 4]);
            }
#pragma unroll
            for (int q = 0; q < 3; q++) {
                int i = q * 256 + t;
                if (i < 640) cpa16(&sB[sn][i * 4], &g_bpk[cn * SB_W + i * 4]);
            }
            cpa_commit();
            cpa_wait<1>();
        } else {
            cpa_wait<0>();
        }
        __syncthreads();

        const float* A = sA[st];
        const float* B = sB[st];
#pragma unroll
        for (int s = 0; s < 4; s++) {
            uint32_t a[2][4];
#pragma unroll
            for (int m = 0; m < 2; m++) {
                int r0 = wid * 32 + m * 16 + g;
                a[m][0] = f2tf32(A[r0 * AST + s * 8 + tig]);
                a[m][1] = f2tf32(A[(r0 + 8) * AST + s * 8 + tig]);
                a[m][2] = f2tf32(A[r0 * AST + s * 8 + tig + 4]);
                a[m][3] = f2tf32(A[(r0 + 8) * AST + s * 8 + tig + 4]);
            }
            const float4* bp = (const float4*)&B[(s * 32 + lane) * 20];
            float4 q0 = bp[0], q1 = bp[1], q2 = bp[2], q3 = bp[3];
            uint32_t b0[8] = {__float_as_uint(q0.x), __float_as_uint(q0.y),
                              __float_as_uint(q0.z), __float_as_uint(q0.w),
                              __float_as_uint(q1.x), __float_as_uint(q1.y),
                              __float_as_uint(q1.z), __float_as_uint(q1.w)};
            uint32_t b1[8] = {__float_as_uint(q2.x), __float_as_uint(q2.y),
                              __float_as_uint(q2.z), __float_as_uint(q2.w),
                              __float_as_uint(q3.x), __float_as_uint(q3.y),
                              __float_as_uint(q3.z), __float_as_uint(q3.w)};
#pragma unroll
            for (int j = 0; j < 8; j++) {
#pragma unroll
                for (int m = 0; m < 2; m++) {
                    asm volatile(
                        "mma.sync.aligned.m16n8k8.row.col.f32.tf32.tf32.f32 "
                        "{%0,%1,%2,%3}, {%4,%5,%6,%7}, {%8,%9}, {%0,%1,%2,%3};"
                        : "+f"(c[m][j][0]), "+f"(c[m][j][1]),
                          "+f"(c[m][j][2]), "+f"(c[m][j][3])
                        : "r"(a[m][0]), "r"(a[m][1]), "r"(a[m][2]), "r"(a[m][3]),
                          "r"(b0[j]), "r"(b1[j]));
                }
            }
        }
        __syncthreads();
    }

    int R[4];
#pragma unroll
    for (int m = 0; m < 4; m++) {
        int r = row0 + m * 8 + g;
        R[m] = (r < NN) ? r : (NN - 1);
    }
    float di[4];
#pragma unroll
    for (int m = 0; m < 4; m++) di[m] = rsqrtf((float)g_cnt[R[m]]);
#pragma unroll
    for (int m = 0; m < 2; m++) {
        int rA = row0 + m * 16 + g;
        int rB = rA + 8;
#pragma unroll
        for (int j = 0; j < 8; j++) {
            int col = j * 8 + 2 * tig;
            if (rA < NN) {
                __half2 v = __floats2half2_rn(c[m][j][0] * di[2 * m],
                                              c[m][j][1] * di[2 * m]);
                *(__half2*)&g_hs1[(size_t)rA * DH + col] = v;
            }
            if (rB < NN) {
                __half2 v = __floats2half2_rn(c[m][j][2] * di[2 * m + 1],
                                              c[m][j][3] * di[2 * m + 1]);
                *(__half2*)&g_hs1[(size_t)rB * DH + col] = v;
            }
        }
    }
}

// ---------------- fused gather + MMA (per GCN layer tail) ----------------
// MODE 0: a = relu(dinv*sum(g_hs1)+b1) -> smem; g_hs2 = fp16(dinv*(a@W2))
// MODE 1: a = dinv*sum(g_hs2)+b2      -> smem; out  = a@Wlin + blin
#define FAST 68                              // fused A smem row stride (words)
#define FUSED_SMEM ((256 * FAST + 8 * 32 * 20) * 4)   // 90112 bytes

template <int MODE>
__global__ __launch_bounds__(256) void k_fused(const float* __restrict__ bpre,
                                               const float* __restrict__ bpost,
                                               float* __restrict__ out) {
    extern __shared__ float sm2[];
    float* aS = sm2;                         // 256 x 68
    float* sB = sm2 + 256 * FAST;            // 5120 words
    int t = threadIdx.x;
    int wid = t >> 5, lane = t & 31;
    int g = lane >> 2, tig = lane & 3;
    int base = blockIdx.x * 256;

    {
        const float4* src = (const float4*)&g_bpk[(64 + MODE * 8) * 640];
        float4* dst = (float4*)sB;
#pragma unroll
        for (int i = 0; i < 5; i++) dst[t + i * 256] = src[t + i * 256];
    }

    const __half* __restrict__ hin = (MODE == 0) ? g_hs1 : g_hs2;
    float2 bp = ((const float2*)bpre)[lane];

    // gather phase: each warp sums 32 nodes into smem rows
    for (int i = 0; i < 32; i++) {
        int node = base + wid * 32 + i;
        if (node >= NN) break;
        int js = g_rowptr[node], je = g_rowptr[node + 1];
        float ax = 0.f, ay = 0.f;
        int j = js;
        for (; j + 32 <= je; j += 32) {
            int myc = g_col[j + lane];
#pragma unroll
            for (int l = 0; l < 32; l++) {
                int s = __shfl_sync(0xffffffffu, myc, l);
                float2 v = __half22float2(*(const __half2*)&hin[s * DH + 2 * lane]);
                ax += v.x; ay += v.y;
            }
        }
        if (j < je) {
            int myc = (j + lane < je) ? g_col[j + lane] : 0;
            int mrem = je - j;
            for (int l = 0; l < mrem; l++) {
                int s = __shfl_sync(0xffffffffu, myc, l);
                float2 v = __half22float2(*(const __half2*)&hin[s * DH + 2 * lane]);
                ax += v.x; ay += v.y;
            }
        }
        float di = g_dinv[node];
        ax = ax * di + bp.x;
        ay = ay * di + bp.y;
        if (MODE == 0) { ax = fmaxf(ax, 0.f); ay = fmaxf(ay, 0.f); }
        int lr = wid * 32 + i;
        aS[lr * FAST + 2 * lane]     = ax;
        aS[lr * FAST + 2 * lane + 1] = ay;
    }
    __syncthreads();

    // MMA phase: warp tile 32 rows x 64 cols, A from smem
    float c[2][8][4];
#pragma unroll
    for (int m = 0; m < 2; m++)
#pragma unroll
        for (int j = 0; j < 8; j++)
#pragma unroll
            for (int q = 0; q < 4; q++) c[m][j][q] = 0.f;

    int w32 = wid * 32;
#pragma unroll
    for (int s = 0; s < 8; s++) {
        int k0 = s * 8;
        uint32_t a[2][4];
#pragma unroll
        for (int m = 0; m < 2; m++) {
            int r0 = w32 + m * 16 + g;
            a[m][0] = f2tf32(aS[r0 * FAST + k0 + tig]);
            a[m][1] = f2tf32(aS[(r0 + 8) * FAST + k0 + tig]);
            a[m][2] = f2tf32(aS[r0 * FAST + k0 + tig + 4]);
            a[m][3] = f2tf32(aS[(r0 + 8) * FAST + k0 + tig + 4]);
        }
        const float4* bpf = (const float4*)&sB[(s * 32 + lane) * 20];
        float4 q0 = bpf[0], q1 = bpf[1], q2 = bpf[2], q3 = bpf[3];
        uint32_t b0[8] = {__float_as_uint(q0.x), __float_as_uint(q0.y),
                          __float_as_uint(q0.z), __float_as_uint(q0.w),
                          __float_as_uint(q1.x), __float_as_uint(q1.y),
                          __float_as_uint(q1.z), __float_as_uint(q1.w)};
        uint32_t b1[8] = {__float_as_uint(q2.x), __float_as_uint(q2.y),
                          __float_as_uint(q2.z), __float_as_uint(q2.w),
                          __float_as_uint(q3.x), __float_as_uint(q3.y),
                          __float_as_uint(q3.z), __float_as_uint(q3.w)};
#pragma unroll
        for (int j = 0; j < 8; j++) {
#pragma unroll
            for (int m = 0; m < 2; m++) {
                asm volatile(
                    "mma.sync.aligned.m16n8k8.row.col.f32.tf32.tf32.f32 "
                    "{%0,%1,%2,%3}, {%4,%5,%6,%7}, {%8,%9}, {%0,%1,%2,%3};"
                    : "+f"(c[m][j][0]), "+f"(c[m][j][1]),
                      "+f"(c[m][j][2]), "+f"(c[m][j][3])
                    : "r"(a[m][0]), "r"(a[m][1]), "r"(a[m][2]), "r"(a[m][3]),
                      "r"(b0[j]), "r"(b1[j]));
            }
        }
    }

    if (MODE == 0) {
#pragma unroll
        for (int m = 0; m < 2; m++) {
            int rA = base + w32 + m * 16 + g, rB = rA + 8;
            float diA = g_dinv[(rA < NN) ? rA : (NN - 1)];
            float diB = g_dinv[(rB < NN) ? rB : (NN - 1)];
#pragma unroll
            for (int j = 0; j < 8; j++) {
                int col = j * 8 + 2 * tig;
                if (rA < NN) {
                    __half2 v = __floats2half2_rn(c[m][j][0] * diA, c[m][j][1] * diA);
                    *(__half2*)&g_hs2[(size_t)rA * DH + col] = v;
                }
                if (rB < NN) {
                    __half2 v = __floats2half2_rn(c[m][j][2] * diB, c[m][j][3] * diB);
                    *(__half2*)&g_hs2[(size_t)rB * DH + col] = v;
                }
            }
        }
    } else {
#pragma unroll
        for (int m = 0; m < 2; m++) {
            int rA = base + w32 + m * 16 + g, rB = rA + 8;
#pragma unroll
            for (int j = 0; j < 8; j++) {
                int col = j * 8 + 2 * tig;
                float2 bq = *(const float2*)&bpost[col];
                if (rA < NN) {
                    float2 v = {c[m][j][0] + bq.x, c[m][j][1] + bq.y};
                    *(float2*)&out[(size_t)rA * DH + col] = v;
                }
                if (rB < NN) {
                    float2 v = {c[m][j][2] + bq.x, c[m][j][3] + bq.y};
                    *(float2*)&out[(size_t)rB * DH + col] = v;
                }
            }
        }
    }
}

extern "C" void kernel_launch(void* const* d_in, const int* in_sizes, int n_in,
                              void* d_out, int out_size) {
    const float* x    = (const float*)d_in[0];
    const int*   ei   = (const int*)d_in[1];
    const float* W1   = (const float*)d_in[2];
    const float* b1   = (const float*)d_in[3];
    const float* W2   = (const float*)d_in[4];
    const float* b2   = (const float*)d_in[5];
    const float* Wlin = (const float*)d_in[6];
    const float* blin = (const float*)d_in[7];
    float* out = (float*)d_out;

    static int smem_set = 0;
    if (!smem_set) {
        cudaFuncSetAttribute(k_gemm1_mma, cudaFuncAttributeMaxDynamicSharedMemorySize, GEMM_SMEM);
        cudaFuncSetAttribute(k_fused<0>, cudaFuncAttributeMaxDynamicSharedMemorySize, FUSED_SMEM);
        cudaFuncSetAttribute(k_fused<1>, cudaFuncAttributeMaxDynamicSharedMemorySize, FUSED_SMEM);
        smem_set = 1;
    }

    k_pack <<<160, 256>>>(W1, W2, Wlin);                         // 0
    k_init <<<(NN + 255) / 256, 256>>>();                        // 1
    k_count<<<(ET + 255) / 256, 256>>>(ei);                      // 2
    k_gemm1_mma<<<(NN + 255) / 256, 256, GEMM_SMEM>>>(x);        // 3 <- ncu
    k_scan1<<<NBLK, 1024>>>();                                   // 4
    k_scan2<<<1, 128>>>();                                       // 5
    k_scan3<<<(NN + 255) / 256, 256>>>();                        // 6
    k_fill <<<(ET + 255) / 256, 256>>>(ei);                      // 7
    k_fused<0><<<(NN + 255) / 256, 256, FUSED_SMEM>>>(b1, nullptr, nullptr);  // 8
    k_fused<1><<<(NN + 255) / 256, 256, FUSED_SMEM>>>(b2, blin, out);         // 9
}

// round 9
// speedup vs baseline: 1.7226x; 1.7226x over previous
#include <cuda_runtime.h>
#include <cuda_fp16.h>
#include <cstdint>

#define NN 100000
#define NE 3200000
#define ET (NE + NN)
#define DIN 512
#define DH 64
#define NBLK 98

__device__ __half g_hs1[(size_t)NN * DH];
__device__ __half g_hs2[(size_t)NN * DH];
__device__ float g_a[(size_t)NN * DH];
__device__ float g_bpk[80 * 32 * 20];
__device__ float g_dinv[NN];
__device__ int   g_cnt[NN];
__device__ int   g_rowptr[NN + 1];
__device__ int   g_cursor[NN];
__device__ int   g_col[ET];
__device__ int   g_bsum[128];

__device__ __forceinline__ uint32_t smem_u32(const void* p) {
    uint32_t a;
    asm("{ .reg .u64 t; cvta.to.shared.u64 t, %1; cvt.u32.u64 %0, t; }" : "=r"(a) : "l"(p));
    return a;
}
__device__ __forceinline__ void cpa16(float* dst, const float* src) {
    uint32_t d = smem_u32(dst);
    asm volatile("cp.async.ca.shared.global [%0], [%1], 16;" :: "r"(d), "l"(src) : "memory");
}
__device__ __forceinline__ void cpa_commit() {
    asm volatile("cp.async.commit_group;" ::: "memory");
}
template <int N> __device__ __forceinline__ void cpa_wait() {
    asm volatile("cp.async.wait_group %0;" :: "n"(N) : "memory");
}
__device__ __forceinline__ uint32_t f2tf32(float f) {
    uint32_t u;
    asm("cvt.rna.tf32.f32 %0, %1;" : "=r"(u) : "f"(f));
    return u;
}

__global__ void k_pack(const float* __restrict__ W1, const float* __restrict__ W2,
                       const float* __restrict__ Wlin) {
    int tid = blockIdx.x * blockDim.x + threadIdx.x;
    if (tid >= 80 * 32 * 16) return;
    int s   = tid >> 9;
    int l   = (tid >> 4) & 31;
    int idx = tid & 15;
    int g = l >> 2, tig = l & 3;
    int j = idx & 7;
    int half = idx >> 3;
    const float* W; int sl;
    if (s < 64)      { W = W1;   sl = s; }
    else if (s < 72) { W = W2;   sl = s - 64; }
    else             { W = Wlin; sl = s - 72; }
    int k = sl * 8 + tig + half * 4;
    float v = W[k * DH + 8 * j + g];
    g_bpk[(s * 32 + l) * 20 + idx] = __uint_as_float(f2tf32(v));
}

__global__ void k_init() {
    int i = blockIdx.x * blockDim.x + threadIdx.x;
    if (i < NN) g_cnt[i] = 0;
}

__global__ void k_count(const int* __restrict__ ei) {
    int e = blockIdx.x * blockDim.x + threadIdx.x;
    if (e >= ET) return;
    int d = (e < NE) ? ei[NE + e] : (e - NE);
    atomicAdd(&g_cnt[d], 1);
}

__global__ void k_scan1() {
    __shared__ int s[1024];
    int i = blockIdx.x * 1024 + threadIdx.x;
    int v = (i < NN) ? g_cnt[i] : 0;
    s[threadIdx.x] = v;
    __syncthreads();
    for (int off = 1; off < 1024; off <<= 1) {
        int t = (threadIdx.x >= off) ? s[threadIdx.x - off] : 0;
        __syncthreads();
        s[threadIdx.x] += t;
        __syncthreads();
    }
    if (i < NN) g_rowptr[i] = s[threadIdx.x] - v;
    if (threadIdx.x == 1023) g_bsum[blockIdx.x] = s[1023];
}

__global__ void k_scan2() {
    __shared__ int s[128];
    int t = threadIdx.x;
    int v = (t < NBLK) ? g_bsum[t] : 0;
    s[t] = v;
    __syncthreads();
    for (int off = 1; off < 128; off <<= 1) {
        int u = (t >= off) ? s[t - off] : 0;
        __syncthreads();
        s[t] += u;
        __syncthreads();
    }
    if (t < NBLK) g_bsum[t] = s[t] - v;
}

__global__ void k_scan3() {
    int i = blockIdx.x * blockDim.x + threadIdx.x;
    if (i == 0) g_rowptr[NN] = ET;
    if (i >= NN) return;
    int r = g_rowptr[i] + g_bsum[i >> 10];
    g_rowptr[i] = r;
    g_cursor[i] = r;
    g_dinv[i]   = rsqrtf((float)g_cnt[i]);
}

__global__ void k_fill(const int* __restrict__ ei) {
    int e = blockIdx.x * blockDim.x + threadIdx.x;
    if (e >= ET) return;
    int s, d;
    if (e < NE) { s = ei[e]; d = ei[NE + e]; } else { s = e - NE; d = s; }
    int pos = atomicAdd(&g_cursor[d], 1);
    g_col[pos] = s;
}

// ---------------- GEMM1 (round-6 config: M=256, 256 thr) ----------------
#define AST 36
#define SA_W (256 * AST)
#define SB_W 2560
#define GEMM_SMEM ((2 * SA_W + 2 * SB_W) * 4)   // 94208

__global__ __launch_bounds__(256) void k_gemm1_mma(const float* __restrict__ x) {
    extern __shared__ float sm[];
    float* sA[2] = {sm, sm + SA_W};
    float* sB[2] = {sm + 2 * SA_W, sm + 2 * SA_W + SB_W};
    int t = threadIdx.x;
    int wid = t >> 5, lane = t & 31;
    int g = lane >> 2, tig = lane & 3;
    int row0 = blockIdx.x * 256 + wid * 32;

    float c[2][8][4];
#pragma unroll
    for (int m = 0; m < 2; m++)
#pragma unroll
        for (int j = 0; j < 8; j++)
#pragma unroll
            for (int q = 0; q < 4; q++) c[m][j][q] = 0.f;

    int arow = t >> 3, ajj = t & 7;
    int argl = blockIdx.x * 256 + arow;

    {
#pragma unroll
        for (int p = 0; p < 8; p++) {
            int row = p * 32 + arow;
            int rg = argl + p * 32; if (rg >= NN) rg = NN - 1;
            cpa16(&sA[0][row * AST + ajj * 4], &x[(size_t)rg * DIN + ajj * 4]);
        }
#pragma unroll
        for (int q = 0; q < 3; q++) {
            int i = q * 256 + t;
            if (i < 640) cpa16(&sB[0][i * 4], &g_bpk[i * 4]);
        }
        cpa_commit();
    }

    for (int ch = 0; ch < 16; ch++) {
        int st = ch & 1;
        if (ch < 15) {
            int cn = ch + 1, sn = cn & 1;
#pragma unroll
            for (int p = 0; p < 8; p++) {
                int row = p * 32 + arow;
                int rg = argl + p * 32; if (rg >= NN) rg = NN - 1;
                cpa16(&sA[sn][row * AST + ajj * 4], &x[(size_t)rg * DIN + cn * 32 + ajj * 4]);
            }
#pragma unroll
            for (int q = 0; q < 3; q++) {
                int i = q * 256 + t;
                if (i < 640) cpa16(&sB[sn][i * 4], &g_bpk[cn * SB_W + i * 4]);
            }
            cpa_commit();
            cpa_wait<1>();
        } else {
            cpa_wait<0>();
        }
        __syncthreads();

        const float* A = sA[st];
        const float* B = sB[st];
#pragma unroll
        for (int s = 0; s < 4; s++) {
            uint32_t a[2][4];
#pragma unroll
            for (int m = 0; m < 2; m++) {
                int r0 = wid * 32 + m * 16 + g;
                a[m][0] = f2tf32(A[r0 * AST + s * 8 + tig]);
                a[m][1] = f2tf32(A[(r0 + 8) * AST + s * 8 + tig]);
                a[m][2] = f2tf32(A[r0 * AST + s * 8 + tig + 4]);
                a[m][3] = f2tf32(A[(r0 + 8) * AST + s * 8 + tig + 4]);
            }
            const float4* bp = (const float4*)&B[(s * 32 + lane) * 20];
            float4 q0 = bp[0], q1 = bp[1], q2 = bp[2], q3 = bp[3];
            uint32_t b0[8] = {__float_as_uint(q0.x), __float_as_uint(q0.y),
                              __float_as_uint(q0.z), __float_as_uint(q0.w),
                              __float_as_uint(q1.x), __float_as_uint(q1.y),
                              __float_as_uint(q1.z), __float_as_uint(q1.w)};
            uint32_t b1[8] = {__float_as_uint(q2.x), __float_as_uint(q2.y),
                              __float_as_uint(q2.z), __float_as_uint(q2.w),
                              __float_as_uint(q3.x), __float_as_uint(q3.y),
                              __float_as_uint(q3.z), __float_as_uint(q3.w)};
#pragma unroll
            for (int j = 0; j < 8; j++) {
#pragma unroll
                for (int m = 0; m < 2; m++) {
                    asm volatile(
                        "mma.sync.aligned.m16n8k8.row.col.f32.tf32.tf32.f32 "
                        "{%0,%1,%2,%3}, {%4,%5,%6,%7}, {%8,%9}, {%0,%1,%2,%3};"
                        : "+f"(c[m][j][0]), "+f"(c[m][j][1]),
                          "+f"(c[m][j][2]), "+f"(c[m][j][3])
                        : "r"(a[m][0]), "r"(a[m][1]), "r"(a[m][2]), "r"(a[m][3]),
                          "r"(b0[j]), "r"(b1[j]));
                }
            }
        }
        __syncthreads();
    }

    int R[4];
#pragma unroll
    for (int m = 0; m < 4; m++) {
        int r = row0 + m * 8 + g;
        R[m] = (r < NN) ? r : (NN - 1);
    }
    float di[4];
#pragma unroll
    for (int m = 0; m < 4; m++) di[m] = rsqrtf((float)g_cnt[R[m]]);
#pragma unroll
    for (int m = 0; m < 2; m++) {
        int rA = row0 + m * 16 + g;
        int rB = rA + 8;
#pragma unroll
        for (int j = 0; j < 8; j++) {
            int col = j * 8 + 2 * tig;
            if (rA < NN) {
                __half2 v = __floats2half2_rn(c[m][j][0] * di[2 * m],
                                              c[m][j][1] * di[2 * m]);
                *(__half2*)&g_hs1[(size_t)rA * DH + col] = v;
            }
            if (rB < NN) {
                __half2 v = __floats2half2_rn(c[m][j][2] * di[2 * m + 1],
                                              c[m][j][3] * di[2 * m + 1]);
                *(__half2*)&g_hs1[(size_t)rB * DH + col] = v;
            }
        }
    }
}

// ---------------- gather-sum (high occupancy, no smem) ----------------
template <int MODE>
__global__ __launch_bounds__(256) void k_aggsum(const float* __restrict__ bpre) {
    int t = threadIdx.x;
    int lane = t & 31;
    int node = blockIdx.x * 8 + (t >> 5);
    if (node >= NN) return;

    const __half* __restrict__ hin = (MODE == 0) ? g_hs1 : g_hs2;
    int js = g_rowptr[node], je = g_rowptr[node + 1];
    float ax = 0.f, ay = 0.f;
    int j = js;
    for (; j + 32 <= je; j += 32) {
        int myc = g_col[j + lane];
#pragma unroll
        for (int l = 0; l < 32; l++) {
            int s = __shfl_sync(0xffffffffu, myc, l);
            float2 v = __half22float2(*(const __half2*)&hin[s * DH + 2 * lane]);
            ax += v.x; ay += v.y;
        }
    }
    if (j < je) {
        int myc = (j + lane < je) ? g_col[j + lane] : 0;
        int m = je - j;
        for (int l = 0; l < m; l++) {
            int s = __shfl_sync(0xffffffffu, myc, l);
            float2 v = __half22float2(*(const __half2*)&hin[s * DH + 2 * lane]);
            ax += v.x; ay += v.y;
        }
    }

    float di = g_dinv[node];
    float2 bp = ((const float2*)bpre)[lane];
    ax = ax * di + bp.x;
    ay = ay * di + bp.y;
    if (MODE == 0) { ax = fmaxf(ax, 0.f); ay = fmaxf(ay, 0.f); }
    float2 o = {ax, ay};
    *(float2*)&g_a[(size_t)node * DH + 2 * lane] = o;
}

// ---------------- mm64 with SMEM-staged A (coalesced -> frag LDS) --------
#define FAST 68
#define MM64_SMEM ((256 * FAST + 8 * 32 * 20) * 4)   // 90112

template <int MODE>
__global__ __launch_bounds__(256) void k_mm64(const float* __restrict__ bpost,
                                              float* __restrict__ out) {
    extern __shared__ float sm2[];
    float* aS = sm2;
    float* sB = sm2 + 256 * FAST;
    int t = threadIdx.x;
    int wid = t >> 5, lane = t & 31;
    int g = lane >> 2, tig = lane & 3;
    int base = blockIdx.x * 256;
    int w32 = wid * 32;

    {
        const float4* src = (const float4*)&g_bpk[(64 + MODE * 8) * 640];
        float4* dst = (float4*)sB;
#pragma unroll
        for (int i = 0; i < 5; i++) dst[t + i * 256] = src[t + i * 256];
    }
    // stage A: coalesced float4 loads, 16 rows per pass
#pragma unroll
    for (int i = 0; i < 16; i++) {
        int lr = i * 16 + (t >> 4);
        int rg = base + lr; if (rg >= NN) rg = NN - 1;
        float4 v = *(const float4*)&g_a[(size_t)rg * DH + (t & 15) * 4];
        *(float4*)&aS[lr * FAST + (t & 15) * 4] = v;
    }
    __syncthreads();

    float c[2][8][4];
#pragma unroll
    for (int m = 0; m < 2; m++)
#pragma unroll
        for (int j = 0; j < 8; j++)
#pragma unroll
            for (int q = 0; q < 4; q++) c[m][j][q] = 0.f;

#pragma unroll
    for (int s = 0; s < 8; s++) {
        int k0 = s * 8;
        uint32_t a[2][4];
#pragma unroll
        for (int m = 0; m < 2; m++) {
            int r0 = w32 + m * 16 + g;
            a[m][0] = f2tf32(aS[r0 * FAST + k0 + tig]);
            a[m][1] = f2tf32(aS[(r0 + 8) * FAST + k0 + tig]);
            a[m][2] = f2tf32(aS[r0 * FAST + k0 + tig + 4]);
            a[m][3] = f2tf32(aS[(r0 + 8) * FAST + k0 + tig + 4]);
        }
        const float4* bpf = (const float4*)&sB[(s * 32 + lane) * 20];
        float4 q0 = bpf[0], q1 = bpf[1], q2 = bpf[2], q3 = bpf[3];
        uint32_t b0[8] = {__float_as_uint(q0.x), __float_as_uint(q0.y),
                          __float_as_uint(q0.z), __float_as_uint(q0.w),
                          __float_as_uint(q1.x), __float_as_uint(q1.y),
                          __float_as_uint(q1.z), __float_as_uint(q1.w)};
        uint32_t b1[8] = {__float_as_uint(q2.x), __float_as_uint(q2.y),
                          __float_as_uint(q2.z), __float_as_uint(q2.w),
                          __float_as_uint(q3.x), __float_as_uint(q3.y),
                          __float_as_uint(q3.z), __float_as_uint(q3.w)};
#pragma unroll
        for (int j = 0; j < 8; j++) {
#pragma unroll
            for (int m = 0; m < 2; m++) {
                asm volatile(
                    "mma.sync.aligned.m16n8k8.row.col.f32.tf32.tf32.f32 "
                    "{%0,%1,%2,%3}, {%4,%5,%6,%7}, {%8,%9}, {%0,%1,%2,%3};"
                    : "+f"(c[m][j][0]), "+f"(c[m][j][1]),
                      "+f"(c[m][j][2]), "+f"(c[m][j][3])
                    : "r"(a[m][0]), "r"(a[m][1]), "r"(a[m][2]), "r"(a[m][3]),
                      "r"(b0[j]), "r"(b1[j]));
            }
        }
    }

    if (MODE == 0) {
#pragma unroll
        for (int m = 0; m < 2; m++) {
            int rA = base + w32 + m * 16 + g, rB = rA + 8;
            float diA = g_dinv[(rA < NN) ? rA : (NN - 1)];
            float diB = g_dinv[(rB < NN) ? rB : (NN - 1)];
#pragma unroll
            for (int j = 0; j < 8; j++) {
                int col = j * 8 + 2 * tig;
                if (rA < NN) {
                    __half2 v = __floats2half2_rn(c[m][j][0] * diA, c[m][j][1] * diA);
                    *(__half2*)&g_hs2[(size_t)rA * DH + col] = v;
                }
                if (rB < NN) {
                    __half2 v = __floats2half2_rn(c[m][j][2] * diB, c[m][j][3] * diB);
                    *(__half2*)&g_hs2[(size_t)rB * DH + col] = v;
                }
            }
        }
    } else {
#pragma unroll
        for (int m = 0; m < 2; m++) {
            int rA = base + w32 + m * 16 + g, rB = rA + 8;
#pragma unroll
            for (int j = 0; j < 8; j++) {
                int col = j * 8 + 2 * tig;
                float2 bq = *(const float2*)&bpost[col];
                if (rA < NN) {
                    float2 v = {c[m][j][0] + bq.x, c[m][j][1] + bq.y};
                    *(float2*)&out[(size_t)rA * DH + col] = v;
                }
                if (rB < NN) {
                    float2 v = {c[m][j][2] + bq.x, c[m][j][3] + bq.y};
                    *(float2*)&out[(size_t)rB * DH + col] = v;
                }
            }
        }
    }
}

// ---------------- launch: fork CSR chain onto side stream ----------------
extern "C" void kernel_launch(void* const* d_in, const int* in_sizes, int n_in,
                              void* d_out, int out_size) {
    const float* x    = (const float*)d_in[0];
    const int*   ei   = (const int*)d_in[1];
    const float* W1   = (const float*)d_in[2];
    const float* b1   = (const float*)d_in[3];
    const float* W2   = (const float*)d_in[4];
    const float* b2   = (const float*)d_in[5];
    const float* Wlin = (const float*)d_in[6];
    const float* blin = (const float*)d_in[7];
    float* out = (float*)d_out;

    static cudaStream_t s2 = nullptr;
    static cudaEvent_t e1 = nullptr, e2 = nullptr;
    if (!s2) {   // created on the uncaptured correctness call
        cudaFuncSetAttribute(k_gemm1_mma, cudaFuncAttributeMaxDynamicSharedMemorySize, GEMM_SMEM);
        cudaFuncSetAttribute(k_mm64<0>, cudaFuncAttributeMaxDynamicSharedMemorySize, MM64_SMEM);
        cudaFuncSetAttribute(k_mm64<1>, cudaFuncAttributeMaxDynamicSharedMemorySize, MM64_SMEM);
        cudaStreamCreateWithFlags(&s2, cudaStreamNonBlocking);
        cudaEventCreateWithFlags(&e1, cudaEventDisableTiming);
        cudaEventCreateWithFlags(&e2, cudaEventDisableTiming);
    }

    k_pack <<<160, 256>>>(W1, W2, Wlin);                       // 0
    k_init <<<(NN + 255) / 256, 256>>>();                      // 1
    k_count<<<(ET + 255) / 256, 256>>>(ei);                    // 2
    cudaEventRecord(e1, 0);
    k_gemm1_mma<<<(NN + 255) / 256, 256, GEMM_SMEM>>>(x);      // 3 <- ncu
    // CSR chain on side stream, overlapped with GEMM1
    cudaStreamWaitEvent(s2, e1, 0);
    k_scan1<<<NBLK, 1024, 0, s2>>>();
    k_scan2<<<1, 128, 0, s2>>>();
    k_scan3<<<(NN + 255) / 256, 256, 0, s2>>>();
    k_fill <<<(ET + 255) / 256, 256, 0, s2>>>(ei);
    cudaEventRecord(e2, s2);
    cudaStreamWaitEvent(0, e2, 0);
    // layer tails (serial dependency chain)
    k_aggsum<0><<<NN / 8 + 1, 256>>>(b1);
    k_mm64<0><<<(NN + 255) / 256, 256, MM64_SMEM>>>(nullptr, nullptr);
    k_aggsum<1><<<NN / 8 + 1, 256>>>(b2);
    k_mm64<1><<<(NN + 255) / 256, 256, MM64_SMEM>>>(blin, out);
}